// round 12
// baseline (speedup 1.0000x reference)
#include <cuda_runtime.h>
#include <cstdint>
#include <math.h>

// ---------------------------------------------------------------------------
// Fused dequant -> multiply -> requant (layout proven by R6-R11 passes):
//   inputs a,b : int32 buffers holding promoted int8 values (67,108,864 elems)
//   scales     : float32[D=1024] each (scale_a, scale_b, scale_out)
//   output     : float32[n + D]; [0,n) = quantized values, [n,n+D) = scale_out
//   out[i] = (float) clip(round_half_even((a*sa)*(b*sb)/so), -128, 127)
//
// R12 vs R11 (127.5us; kernel 120.1us, DRAM 80.9%):
//   Evidence across R10/R11: DRAM% pinned at ~81% whether outstanding bytes
//   are 128KB/SM (registers) or 192KB/SM (cp.async) -> mixed 2R:1W stream
//   turnaround wall at ~6.5TB/s. This round only removes loop overhead:
//   * hot loop split into full phase (unconditional refill) + drain phase
//     (empty commits keep wait_group accounting exact) -- kills the
//     per-iteration bounds compare/branch;
//   * per-stage smem addresses hoisted out of the loop.
// ---------------------------------------------------------------------------

#define NSTAGE 3

__device__ __forceinline__ float requant1(float prod, float c) {
    float q = rintf(prod * c);                    // round half to even
    return fminf(fmaxf(q, -128.0f), 127.0f);
}

__device__ __forceinline__ void cp16(uint32_t dst_smem, const void* src) {
    asm volatile("cp.async.cg.shared.global [%0], [%1], 16;"
                 :: "r"(dst_smem), "l"(src));
}
__device__ __forceinline__ void cp_commit() {
    asm volatile("cp.async.commit_group;");
}
template <int N> __device__ __forceinline__ void cp_wait() {
    asm volatile("cp.async.wait_group %0;" :: "n"(N));
}

// vec = 4 elements/thread/stage; smem = NSTAGE x (a:4KB + b:4KB) = 24KB/block
__global__ void __launch_bounds__(256, 8)
main_cp(const int* __restrict__ a, const int* __restrict__ b,
        const float* __restrict__ sa, const float* __restrict__ sb,
        const float* __restrict__ so, float* __restrict__ out,
        int n_vec, int vec_per_row, int n, int tail, int D) {
    __shared__ __align__(16) int sm[NSTAGE][2][256 * 4];

    const int tid = blockIdx.x * blockDim.x + threadIdx.x;
    const int T   = gridDim.x * blockDim.x;   // multiple of vec_per_row
    const int dbase = (tid % vec_per_row) * 4;

    // fused tuple tail: echo scale_out into out[n .. n+tail)
    if (tid < tail) out[n + tid] = (tid < D) ? so[tid] : 0.0f;

    float C[4];
#pragma unroll
    for (int k = 0; k < 4; k++)
        C[k] = __fdiv_rn(sa[dbase + k] * sb[dbase + k], so[dbase + k]);

    // per-stage private smem slot addresses, hoisted
    uint32_t sa_sm[NSTAGE], sb_sm[NSTAGE];
#pragma unroll
    for (int s = 0; s < NSTAGE; s++) {
        sa_sm[s] = (uint32_t)__cvta_generic_to_shared(&sm[s][0][threadIdx.x * 4]);
        sb_sm[s] = (uint32_t)__cvta_generic_to_shared(&sm[s][1][threadIdx.x * 4]);
    }

    // prologue: fill NSTAGE stages
    int v = tid;
#pragma unroll
    for (int s = 0; s < NSTAGE; s++) {
        if (v < n_vec) {
            cp16(sa_sm[s], a + (size_t)v * 4);
            cp16(sb_sm[s], b + (size_t)v * 4);
        }
        cp_commit();
        v += T;
    }

    float4* __restrict__ ov = reinterpret_cast<float4*>(out);

    // full phase: refill guaranteed in range (v = vp + NSTAGE*T < n_vec)
    const long long full_end =
        (long long)n_vec - (long long)NSTAGE * (long long)T;
    int s = 0;
    int vp = tid;
    for (; vp < full_end; vp += T) {
        cp_wait<NSTAGE - 1>();
        const int4 ia = *reinterpret_cast<const int4*>(&sm[s][0][threadIdx.x * 4]);
        const int4 ib = *reinterpret_cast<const int4*>(&sm[s][1][threadIdx.x * 4]);

        float4 o;
        o.x = requant1((float)(ia.x * ib.x), C[0]);
        o.y = requant1((float)(ia.y * ib.y), C[1]);
        o.z = requant1((float)(ia.z * ib.z), C[2]);
        o.w = requant1((float)(ia.w * ib.w), C[3]);
        __stcs(&ov[vp], o);

        cp16(sa_sm[s], a + (size_t)v * 4);
        cp16(sb_sm[s], b + (size_t)v * 4);
        cp_commit();
        v += T;
        s = (s + 1 == NSTAGE) ? 0 : s + 1;
    }

    // drain phase: last <=NSTAGE iterations, empty commits keep counts exact
    for (; vp < n_vec; vp += T) {
        cp_wait<NSTAGE - 1>();
        const int4 ia = *reinterpret_cast<const int4*>(&sm[s][0][threadIdx.x * 4]);
        const int4 ib = *reinterpret_cast<const int4*>(&sm[s][1][threadIdx.x * 4]);

        float4 o;
        o.x = requant1((float)(ia.x * ib.x), C[0]);
        o.y = requant1((float)(ia.y * ib.y), C[1]);
        o.z = requant1((float)(ia.z * ib.z), C[2]);
        o.w = requant1((float)(ia.w * ib.w), C[3]);
        __stcs(&ov[vp], o);

        cp_commit();   // empty group
        s = (s + 1 == NSTAGE) ? 0 : s + 1;
    }
}

// Proven R10 256-bit register path, kept as dispatch fallback.
__global__ void __launch_bounds__(256, 8)
main_v8(const int* __restrict__ a, const int* __restrict__ b,
        const float* __restrict__ sa, const float* __restrict__ sb,
        const float* __restrict__ so, float* __restrict__ out,
        int n_vec, int vec_per_row, int n, int tail, int D) {
    const int tid = blockIdx.x * blockDim.x + threadIdx.x;
    const int T   = gridDim.x * blockDim.x;
    const int dbase = (tid % vec_per_row) * 8;

    if (tid < tail) out[n + tid] = (tid < D) ? so[tid] : 0.0f;

    float C[8];
#pragma unroll
    for (int k = 0; k < 8; k++)
        C[k] = __fdiv_rn(sa[dbase + k] * sb[dbase + k], so[dbase + k]);

    for (int v = tid; v < n_vec; v += T) {
        const int* pa = a + (size_t)v * 8;
        const int* pb = b + (size_t)v * 8;
        float* po = out + (size_t)v * 8;

        unsigned A[8], B[8];
        asm("ld.global.cs.v8.b32 {%0,%1,%2,%3,%4,%5,%6,%7}, [%8];"
            : "=r"(A[0]), "=r"(A[1]), "=r"(A[2]), "=r"(A[3]),
              "=r"(A[4]), "=r"(A[5]), "=r"(A[6]), "=r"(A[7]) : "l"(pa));
        asm("ld.global.cs.v8.b32 {%0,%1,%2,%3,%4,%5,%6,%7}, [%8];"
            : "=r"(B[0]), "=r"(B[1]), "=r"(B[2]), "=r"(B[3]),
              "=r"(B[4]), "=r"(B[5]), "=r"(B[6]), "=r"(B[7]) : "l"(pb));

        unsigned R[8];
#pragma unroll
        for (int k = 0; k < 8; k++) {
            const int p = (int)A[k] * (int)B[k];
            R[k] = __float_as_uint(requant1((float)p, C[k]));
        }
        asm volatile("st.global.cs.v8.b32 [%0], {%1,%2,%3,%4,%5,%6,%7,%8};"
                     :: "l"(po),
                        "r"(R[0]), "r"(R[1]), "r"(R[2]), "r"(R[3]),
                        "r"(R[4]), "r"(R[5]), "r"(R[6]), "r"(R[7]) : "memory");
    }
}

// Generic fallback for shapes where the fast paths' divisibility fails.
__global__ void __launch_bounds__(256)
main_generic(const int* __restrict__ a, const int* __restrict__ b,
             const float* __restrict__ sa, const float* __restrict__ sb,
             const float* __restrict__ so, float* __restrict__ out,
             int n, int D, int tail) {
    const int tid = blockIdx.x * blockDim.x + threadIdx.x;
    const int T   = gridDim.x * blockDim.x;
    if (tid < tail) out[n + tid] = (tid < D) ? so[tid] : 0.0f;
    for (int i = tid; i < n; i += T) {
        const int d = i % D;
        float c = __fdiv_rn(__ldg(&sa[d]) * __ldg(&sb[d]), __ldg(&so[d]));
        out[i] = requant1((float)(a[i] * b[i]), c);
    }
}

extern "C" void kernel_launch(void* const* d_in, const int* in_sizes, int n_in,
                              void* d_out, int out_size) {
    // Identify inputs by element count (ordering-agnostic; a*b and sa*sb
    // commute; scale_out is the last small input in dict AND alpha order).
    long long nmax = 0;
    for (int i = 0; i < n_in; i++)
        if ((long long)in_sizes[i] > nmax) nmax = in_sizes[i];

    const int* big[2] = {nullptr, nullptr};
    const float* scl[3] = {nullptr, nullptr, nullptr};
    int nbig = 0, nscl = 0, D = 0;
    for (int i = 0; i < n_in; i++) {
        if ((long long)in_sizes[i] == nmax && nbig < 2) {
            big[nbig++] = (const int*)d_in[i];
        } else if (nscl < 3) {
            scl[nscl++] = (const float*)d_in[i];
            D = in_sizes[i];
        }
    }
    const int* a = big[0];
    const int* b = big[1] ? big[1] : big[0];
    const float* sa = scl[0];
    const float* sb = scl[1] ? scl[1] : scl[0];
    const float* so = scl[2] ? scl[2] : (scl[1] ? scl[1] : scl[0]);
    float* out = (float*)d_out;

    const int n = (int)nmax;                 // 67,108,864 elements
    if (D <= 0) D = 1024;

    long long tail64 = (long long)out_size - (long long)n;
    if (tail64 < 0) tail64 = 0;

    const int blocks = 1184, threads = 256;  // 8 blocks/SM x 148 SMs, 1 wave
    const long long T = (long long)blocks * threads;   // 303104
    int tail = (int)(tail64 > T ? T : tail64);

    if ((D % 4) == 0 && (n % 4) == 0 && (T % (D / 4)) == 0) {
        main_cp<<<blocks, threads>>>(a, b, sa, sb, so, out,
                                     n / 4, D / 4, n, tail, D);
    } else if ((D % 8) == 0 && (n % 8) == 0 && (T % (D / 8)) == 0) {
        main_v8<<<blocks, threads>>>(a, b, sa, sb, so, out,
                                     n / 8, D / 8, n, tail, D);
    } else {
        main_generic<<<blocks, threads>>>(a, b, sa, sb, so, out, n, D, tail);
    }
}